// round 1
// baseline (speedup 1.0000x reference)
#include <cuda_runtime.h>
#include <math.h>
#include <stdint.h>

#define T_  256
#define B_  64
#define H_  768
#define NH_ 12
#define HD_ 64
#define G4H (4*H_)          // 3072
#define QKVW (3*H_)         // 2304
#define GRID 148
#define NTHREADS 256

// ------------------------- device scratch (static, no runtime alloc) -------
__device__ float g_newvAll[T_*B_*H_];          // newv per step (== mutated inputs)
__device__ float g_pair[2*B_*H_];              // gathered [left,right] rows, m = b*2+s
__device__ float g_qkvp[4*2*B_*QKVW];          // 4 split-K partials of (128 x 2304)
__device__ float g_ctx[B_*2*H_];               // attention context (B x 1536)
__device__ float g_fusep[24*B_*H_];            // 24 split-K partials of (64 x 768)
__device__ float g_p6[6*B_*G4H];               // 6 split-K partials of (64 x 3072)
__device__ float g_base[B_*G4H];
__device__ float g_h[B_*H_];
__device__ float g_c[B_*H_];
__device__ unsigned g_cnt = 0;
__device__ unsigned g_gen = 0;

// ------------------------- grid-wide barrier -------------------------------
__device__ __forceinline__ void gsync() {
    __syncthreads();
    if (threadIdx.x == 0) {
        __threadfence();                         // release + L1D invalidate (CCTL.IVALL)
        unsigned g = atomicAdd(&g_gen, 0u);
        unsigned a = atomicAdd(&g_cnt, 1u);
        if (a == gridDim.x - 1u) {
            atomicExch(&g_cnt, 0u);
            __threadfence();
            atomicExch(&g_gen, g + 1u);
        } else {
            while (atomicAdd(&g_gen, 0u) == g) { }
        }
        __threadfence();                         // acquire side
    }
    __syncthreads();
}

__device__ __forceinline__ float wsum(float v) {
    #pragma unroll
    for (int o = 16; o > 0; o >>= 1) v += __shfl_xor_sync(0xffffffffu, v, o);
    return v;
}
__device__ __forceinline__ float sigm(float v) { return 1.f / (1.f + expf(-v)); }

// ------------------------- SIMT GEMM: C(64x128) += A(64xK) @ W(Kx128) ------
// A row m, col k:  k < kBound ? A0[m*lda + k] : A1[m*lda + k-kBound]
// W row k, col n:  k < kBound ? W0[k*ldw + n] : W1[(k-kBound)*ldw + n]
// (W0/W1 pre-offset by the global column; A0 pre-offset by the row tile)
__device__ void gemm64(float As[16][64], float Bs[16][128],
                       const float* __restrict__ A0, const float* __restrict__ A1,
                       int lda, int kBound,
                       const float* __restrict__ W0, const float* __restrict__ W1, int ldw,
                       int kStart, int kCount,
                       float* __restrict__ C, int ldc)
{
    const int tid = threadIdx.x;
    const int tx = tid & 15;         // 16 col groups (8 cols each)
    const int ty = tid >> 4;         // 16 row groups (4 rows each)
    const int am = tid >> 2;         // A load: row
    const int ak = (tid & 3) << 2;   // A load: 4 consecutive k
    const int wk = tid >> 4;         // W load: k row
    const int wn = (tid & 15) << 3;  // W load: 8 consecutive n

    float acc[4][8];
    #pragma unroll
    for (int i = 0; i < 4; i++)
        #pragma unroll
        for (int j = 0; j < 8; j++) acc[i][j] = 0.f;

    for (int kt = 0; kt < kCount; kt += 16) {
        const int kg = kStart + kt;
        {   // stage A tile (transposed into smem)
            int k = kg + ak;
            const float* src = (k < kBound) ? (A0 + (size_t)am * lda + k)
                                            : (A1 + (size_t)am * lda + (k - kBound));
            float4 v = *(const float4*)src;
            As[ak + 0][am] = v.x; As[ak + 1][am] = v.y;
            As[ak + 2][am] = v.z; As[ak + 3][am] = v.w;
        }
        {   // stage W tile
            int k = kg + wk;
            const float* src = (k < kBound) ? (W0 + (size_t)k * ldw + wn)
                                            : (W1 + (size_t)(k - kBound) * ldw + wn);
            float4 v0 = *(const float4*)(src);
            float4 v1 = *(const float4*)(src + 4);
            *(float4*)&Bs[wk][wn]     = v0;
            *(float4*)&Bs[wk][wn + 4] = v1;
        }
        __syncthreads();
        #pragma unroll
        for (int k = 0; k < 16; k++) {
            float a[4], b[8];
            *(float4*)a       = *(const float4*)&As[k][ty << 2];
            *(float4*)b       = *(const float4*)&Bs[k][tx << 3];
            *(float4*)(b + 4) = *(const float4*)&Bs[k][(tx << 3) + 4];
            #pragma unroll
            for (int i = 0; i < 4; i++)
                #pragma unroll
                for (int j = 0; j < 8; j++)
                    acc[i][j] = fmaf(a[i], b[j], acc[i][j]);
        }
        __syncthreads();
    }
    #pragma unroll
    for (int i = 0; i < 4; i++) {
        float* dst = C + (size_t)((ty << 2) + i) * ldc + (tx << 3);
        *(float4*)(dst)     = make_float4(acc[i][0], acc[i][1], acc[i][2], acc[i][3]);
        *(float4*)(dst + 4) = make_float4(acc[i][4], acc[i][5], acc[i][6], acc[i][7]);
    }
}

// gather pair rows for step tnext: left = inputs[clip(ping[b][tnext]-1)], right = inputs[tnext]
// inputs[i] == g_newvAll[i] if i < tnext (already rewritten), else x[i]
__device__ void gather_pair(int tnext, const float* __restrict__ x, const int* __restrict__ ping)
{
    const int idx0 = blockIdx.x * blockDim.x + threadIdx.x;
    const int stride = gridDim.x * blockDim.x;
    for (int idx = idx0; idx < 2 * B_ * H_; idx += stride) {
        int m = idx / H_, k = idx - m * H_;
        int b = m >> 1, s = m & 1;
        float val;
        if (s) {
            val = x[((size_t)tnext * B_ + b) * H_ + k];
        } else {
            int pt = ping[b * T_ + tnext];
            int i2 = pt - 1;
            i2 = i2 < 0 ? 0 : (i2 > T_ - 1 ? T_ - 1 : i2);
            const float* src = (i2 < tnext) ? g_newvAll : x;
            val = src[((size_t)i2 * B_ + b) * H_ + k];
        }
        g_pair[idx] = val;
    }
}

// ------------------------- persistent kernel -------------------------------
__global__ void __launch_bounds__(NTHREADS)
sqac_kernel(const float* __restrict__ question, const float* __restrict__ answer,
            const float* __restrict__ x, const int* __restrict__ ping,
            const float* __restrict__ h0, const float* __restrict__ c0,
            const float* __restrict__ Wqh, const float* __restrict__ bqh,
            const float* __restrict__ Wah, const float* __restrict__ bah,
            const float* __restrict__ Wih, const float* __restrict__ bih,
            const float* __restrict__ Whh, const float* __restrict__ bhh,
            const float* __restrict__ Wq,  const float* __restrict__ bq,
            const float* __restrict__ Wk,  const float* __restrict__ bk,
            const float* __restrict__ Wv,  const float* __restrict__ bv,
            const float* __restrict__ Wfuse, const float* __restrict__ bfuse,
            float* __restrict__ out)
{
    __shared__ float As[16][64];
    __shared__ float Bs[16][128];

    const int idx0   = blockIdx.x * blockDim.x + threadIdx.x;
    const int stride = gridDim.x * blockDim.x;
    const int bid    = blockIdx.x;

    // ---- I0: state init + first gather --------------------------------
    for (int idx = idx0; idx < B_ * H_; idx += stride) {
        g_h[idx] = h0[idx];
        g_c[idx] = c0[idx];
    }
    gather_pair(0, x, ping);
    gsync();

    // ---- I1: base = question@Wqh + answer@Wah (64x3072, K=1536, splitK=6)
    if (bid < 144) {
        int kc = bid / 24, nt = bid % 24;
        gemm64(As, Bs, question, answer, H_, H_,
               Wqh + nt * 128, Wah + nt * 128, G4H,
               kc * 256, 256, g_p6 + (size_t)kc * (B_ * G4H) + nt * 128, G4H);
    }
    gsync();

    // ---- I2: combine base + biases -------------------------------------
    for (int idx = idx0; idx < B_ * G4H; idx += stride) {
        int n = idx % G4H;
        float s = bqh[n] + bah[n] + bih[n] + bhh[n];
        #pragma unroll
        for (int kc = 0; kc < 6; kc++) s += g_p6[(size_t)kc * (B_ * G4H) + idx];
        g_base[idx] = s;
    }
    gsync();

    // =====================================================================
    for (int t = 0; t < T_; t++) {
        // ---- A: QKV GEMM, C(128 x 2304), K=768, splitK=4 ----------------
        if (bid < 144) {
            int kc = bid / 36, r = bid % 36;
            int mt = r / 18, nt = r % 18;
            int n0 = nt * 128;
            int wsel = n0 / H_;
            int ncol = n0 - wsel * H_;
            const float* Wb = (wsel == 0) ? Wq : ((wsel == 1) ? Wk : Wv);
            gemm64(As, Bs, g_pair + (size_t)mt * 64 * H_, g_pair, H_, 1 << 28,
                   Wb + ncol, Wb + ncol, H_,
                   kc * 192, 192,
                   g_qkvp + (size_t)kc * (2 * B_ * QKVW) + (size_t)(mt * 64) * QKVW + n0, QKVW);
        }
        gsync();

        // ---- B: attention (one warp per (b, head)) ----------------------
        {
            int wid = bid * (NTHREADS / 32) + (threadIdx.x >> 5);
            int lane = threadIdx.x & 31;
            for (int task = wid; task < B_ * NH_; task += gridDim.x * (NTHREADS / 32)) {
                int b = task / NH_, h = task - b * NH_;
                float q[2][2], kk2[2][2], vv[2][2];
                #pragma unroll
                for (int s = 0; s < 2; s++) {
                    int row = (b * 2 + s) * QKVW;
                    #pragma unroll
                    for (int dd = 0; dd < 2; dd++) {
                        int d = lane + dd * 32;
                        int col = h * HD_ + d;
                        float qv = bq[col], kv = bk[col], vvv = bv[col];
                        #pragma unroll
                        for (int kc = 0; kc < 4; kc++) {
                            const float* p = g_qkvp + (size_t)kc * (2 * B_ * QKVW) + row;
                            qv  += p[col];
                            kv  += p[H_ + col];
                            vvv += p[2 * H_ + col];
                        }
                        q[s][dd] = qv; kk2[s][dd] = kv; vv[s][dd] = vvv;
                    }
                }
                float s00 = wsum(q[0][0]*kk2[0][0] + q[0][1]*kk2[0][1]) * 0.125f;
                float s01 = wsum(q[0][0]*kk2[1][0] + q[0][1]*kk2[1][1]) * 0.125f;
                float s10 = wsum(q[1][0]*kk2[0][0] + q[1][1]*kk2[0][1]) * 0.125f;
                float s11 = wsum(q[1][0]*kk2[1][0] + q[1][1]*kk2[1][1]) * 0.125f;
                float m0 = fmaxf(s00, s01), m1 = fmaxf(s10, s11);
                float e00 = expf(s00 - m0), e01 = expf(s01 - m0);
                float e10 = expf(s10 - m1), e11 = expf(s11 - m1);
                float r0 = 1.f / (e00 + e01), r1 = 1.f / (e10 + e11);
                float p00 = e00 * r0, p01 = e01 * r0, p10 = e10 * r1, p11 = e11 * r1;
                #pragma unroll
                for (int dd = 0; dd < 2; dd++) {
                    int d = lane + dd * 32;
                    g_ctx[b * (2*H_) + h * HD_ + d]       = p00 * vv[0][dd] + p01 * vv[1][dd];
                    g_ctx[b * (2*H_) + H_ + h * HD_ + d]  = p10 * vv[0][dd] + p11 * vv[1][dd];
                }
            }
        }
        gsync();

        // ---- C: fuse GEMM, C(64 x 768), K=1536, splitK=24 ----------------
        if (bid < 144) {
            int kc = bid / 6, nt = bid % 6;
            gemm64(As, Bs, g_ctx, g_ctx, 2 * H_, 1 << 28,
                   Wfuse + nt * 128, Wfuse + nt * 128, H_,
                   kc * 64, 64, g_fusep + (size_t)kc * (B_ * H_) + nt * 128, H_);
        }
        gsync();

        // ---- C2: combine + select + write newvAll[t] --------------------
        for (int idx = idx0; idx < B_ * H_; idx += stride) {
            int b = idx / H_, j = idx - b * H_;
            float e = bfuse[j];
            #pragma unroll
            for (int kc = 0; kc < 24; kc++) e += g_fusep[(size_t)kc * (B_ * H_) + idx];
            int pt = ping[b * T_ + t];
            float right = x[((size_t)t * B_ + b) * H_ + j];
            bool cond = (pt > 0) && (t > 0);
            g_newvAll[(size_t)t * (B_ * H_) + idx] = cond ? e : right;
        }
        gsync();

        // ---- D: gates GEMM, C(64 x 3072), A=[newv|h], K=1536, splitK=6 --
        if (bid < 144) {
            int kc = bid / 24, nt = bid % 24;
            gemm64(As, Bs, g_newvAll + (size_t)t * (B_ * H_), g_h, H_, H_,
                   Wih + nt * 128, Whh + nt * 128, G4H,
                   kc * 256, 256, g_p6 + (size_t)kc * (B_ * G4H) + nt * 128, G4H);
        }
        gsync();

        // ---- E: LSTM pointwise + output + gather next pair --------------
        for (int idx = idx0; idx < B_ * H_; idx += stride) {
            int b = idx / H_, j = idx - b * H_;
            float gg[4];
            #pragma unroll
            for (int u = 0; u < 4; u++) {
                int col = b * G4H + u * H_ + j;
                float s = g_base[col];
                #pragma unroll
                for (int kc = 0; kc < 6; kc++) s += g_p6[(size_t)kc * (B_ * G4H) + col];
                gg[u] = s;
            }
            float iv = sigm(gg[0]);
            float fv = sigm(gg[1]);
            float gv = tanhf(gg[2]);
            float ov = sigm(gg[3]);
            float c = fv * g_c[idx] + iv * gv;
            float h = ov * tanhf(c);
            g_c[idx] = c;
            g_h[idx] = h;
            out[((size_t)t * B_ + b) * H_ + j] = h;
            if (t == T_ - 1) {
                out[((size_t)T_ * B_ + b) * H_ + j]       = h;   // hT
                out[((size_t)(T_ + 1) * B_ + b) * H_ + j] = c;   // cT
            }
        }
        if (t + 1 < T_) gather_pair(t + 1, x, ping);
        gsync();
    }
}

// ------------------------- host launch --------------------------------------
extern "C" void kernel_launch(void* const* d_in, const int* in_sizes, int n_in,
                              void* d_out, int out_size)
{
    (void)in_sizes; (void)n_in; (void)out_size;
    const float* question = (const float*)d_in[0];
    const float* answer   = (const float*)d_in[1];
    const float* x        = (const float*)d_in[2];
    const int*   ping     = (const int*)  d_in[3];
    const float* h0       = (const float*)d_in[4];
    const float* c0       = (const float*)d_in[5];
    const float* Wqh      = (const float*)d_in[6];
    const float* bqh      = (const float*)d_in[7];
    const float* Wah      = (const float*)d_in[8];
    const float* bah      = (const float*)d_in[9];
    const float* Wih      = (const float*)d_in[10];
    const float* bih      = (const float*)d_in[11];
    const float* Whh      = (const float*)d_in[12];
    const float* bhh      = (const float*)d_in[13];
    const float* Wq       = (const float*)d_in[14];
    const float* bq       = (const float*)d_in[15];
    const float* Wk       = (const float*)d_in[16];
    const float* bk       = (const float*)d_in[17];
    const float* Wv       = (const float*)d_in[18];
    const float* bv       = (const float*)d_in[19];
    const float* Wfuse    = (const float*)d_in[20];
    const float* bfuse    = (const float*)d_in[21];

    sqac_kernel<<<GRID, NTHREADS>>>(question, answer, x, ping, h0, c0,
                                    Wqh, bqh, Wah, bah, Wih, bih, Whh, bhh,
                                    Wq, bq, Wk, bk, Wv, bv, Wfuse, bfuse,
                                    (float*)d_out);
}

// round 2
// speedup vs baseline: 1.2388x; 1.2388x over previous
#include <cuda_runtime.h>
#include <math.h>
#include <stdint.h>

#define T_  256
#define B_  64
#define H_  768
#define NH_ 12
#define HD_ 64
#define G4H 3072
#define QKVW 2304
#define NTHREADS 256

// task decompositions
#define SK_QKV 8     // QKV:   18 n-tiles(128) x 8  = 144 tasks, K=96 each
#define SK_G   24    // gates: 12 n-tiles(256) x 24 = 288 tasks, K=64 each
#define SK_F   48    // fuse:   3 n-tiles(256) x 48 = 144 tasks, K=32 each

// ------------------------- device scratch ----------------------------------
__device__ __align__(256) float g_newvAll[T_*B_*H_];
__device__ __align__(256) float g_pair[2*B_*H_];
__device__ __align__(256) float g_qkvp[SK_QKV * 2*B_ * QKVW];
__device__ __align__(256) float g_ctx[B_*2*H_];
__device__ __align__(256) float g_fp[SK_F * B_ * H_];
__device__ __align__(256) float g_gp[SK_G * B_ * G4H];
__device__ __align__(256) float g_base[B_*G4H];
__device__ __align__(256) float g_h[B_*H_];
__device__ __align__(256) float g_c[B_*H_];
__device__ unsigned g_cnt = 0;
__device__ unsigned g_gen = 0;

// ------------------------- grid-wide barrier -------------------------------
__device__ __forceinline__ void gsync() {
    __syncthreads();
    if (threadIdx.x == 0) {
        __threadfence();
        unsigned g = *(volatile unsigned*)&g_gen;
        unsigned a = atomicAdd(&g_cnt, 1u);
        if (a == gridDim.x - 1u) {
            *(volatile unsigned*)&g_cnt = 0u;
            __threadfence();
            *(volatile unsigned*)&g_gen = g + 1u;
        } else {
            while (*(volatile unsigned*)&g_gen == g) { }
        }
        __threadfence();
    }
    __syncthreads();
}

__device__ __forceinline__ float wsum(float v) {
    #pragma unroll
    for (int o = 16; o > 0; o >>= 1) v += __shfl_xor_sync(0xffffffffu, v, o);
    return v;
}
__device__ __forceinline__ float sigm(float v) { return 1.f / (1.f + expf(-v)); }

// ------------------------- packed f32x2 helpers ----------------------------
__device__ __forceinline__ uint64_t bcast2(float f) {
    uint32_t u = __float_as_uint(f);
    uint64_t r;
    asm("mov.b64 %0, {%1,%1};" : "=l"(r) : "r"(u));
    return r;
}
__device__ __forceinline__ void fma2(uint64_t& d, uint64_t a, uint64_t b) {
    asm("fma.rn.f32x2 %0, %1, %2, %0;" : "+l"(d) : "l"(a), "l"(b));
}
__device__ __forceinline__ void lds_v2u64(uint64_t& x, uint64_t& y, const float* p) {
    uint32_t a = (uint32_t)__cvta_generic_to_shared(p);
    asm("ld.shared.v2.u64 {%0,%1}, [%2];" : "=l"(x), "=l"(y) : "r"(a));
}

// ------------------------- double-buffered SIMT GEMM ------------------------
// C(TM x TN) = A(TM x K) @ W(K x TN), per-thread 8x8 tile via fma.rn.f32x2.
// A row m col k: k<kBound ? A0[m*lda+k] : A1[m*lda+(k-kBound)]
// W row k col n: k<kBound ? W0[k*ldw+n] : W1[(k-kBound)*ldw+n]  (W pre-offset by n0)
template<int TM, int TN>
__device__ void gemm_db(float* AsBuf, float* BsBuf,
    const float* __restrict__ A0, const float* __restrict__ A1, int lda, int kBound,
    const float* __restrict__ W0, const float* __restrict__ W1, int ldw,
    int kStart, int kCount, float* __restrict__ C, int ldc)
{
    const int tid = threadIdx.x;
    const int tx = tid % (TN / 8);
    const int ty = tid / (TN / 8);

    // A staging: each thread loads (TM/64) float4s (4 k for one row), stores transposed
    const int am = tid >> 2;
    const int ak = (tid & 3) << 2;
    // B staging
    const int wrow = tid / (TN / 4);
    const int wcol = (tid % (TN / 4)) * 4;
    constexpr int WPASS = NTHREADS / (TN / 4);   // rows per pass

    uint64_t acc[8][4];
    #pragma unroll
    for (int i = 0; i < 8; i++)
        #pragma unroll
        for (int j = 0; j < 4; j++) acc[i][j] = 0ull;

    auto stageA = [&](int buf, int kg) {
        #pragma unroll
        for (int r = 0; r < TM / 64; r++) {
            int row = am + r * 64;
            int k = kg + ak;
            const float* src = (k < kBound) ? (A0 + (size_t)row * lda + k)
                                            : (A1 + (size_t)row * lda + (k - kBound));
            float4 v = *(const float4*)src;
            float* d = AsBuf + buf * (16 * TM);
            d[(ak + 0) * TM + row] = v.x;
            d[(ak + 1) * TM + row] = v.y;
            d[(ak + 2) * TM + row] = v.z;
            d[(ak + 3) * TM + row] = v.w;
        }
    };
    auto stageB = [&](int buf, int kg) {
        #pragma unroll
        for (int r = 0; r < 16 / WPASS; r++) {
            int kr = wrow + r * WPASS;
            int k = kg + kr;
            const float* src = (k < kBound) ? (W0 + (size_t)k * ldw + wcol)
                                            : (W1 + (size_t)(k - kBound) * ldw + wcol);
            *(float4*)(BsBuf + buf * (16 * TN) + kr * TN + wcol) = *(const float4*)src;
        }
    };

    const int ntiles = kCount >> 4;
    stageA(0, kStart);
    stageB(0, kStart);
    __syncthreads();

    for (int t = 0; t < ntiles; t++) {
        const int cur = t & 1;
        if (t + 1 < ntiles) {
            stageA(cur ^ 1, kStart + (t + 1) * 16);
            stageB(cur ^ 1, kStart + (t + 1) * 16);
        }
        const float* Asb = AsBuf + cur * (16 * TM);
        const float* Bsb = BsBuf + cur * (16 * TN);
        #pragma unroll
        for (int k = 0; k < 16; k++) {
            float4 af0 = *(const float4*)(Asb + k * TM + ty * 8);
            float4 af1 = *(const float4*)(Asb + k * TM + ty * 8 + 4);
            uint64_t a[8];
            a[0] = bcast2(af0.x); a[1] = bcast2(af0.y);
            a[2] = bcast2(af0.z); a[3] = bcast2(af0.w);
            a[4] = bcast2(af1.x); a[5] = bcast2(af1.y);
            a[6] = bcast2(af1.z); a[7] = bcast2(af1.w);
            uint64_t b0, b1, b2, b3;
            lds_v2u64(b0, b1, Bsb + k * TN + tx * 8);
            lds_v2u64(b2, b3, Bsb + k * TN + tx * 8 + 4);
            #pragma unroll
            for (int i = 0; i < 8; i++) {
                fma2(acc[i][0], a[i], b0);
                fma2(acc[i][1], a[i], b1);
                fma2(acc[i][2], a[i], b2);
                fma2(acc[i][3], a[i], b3);
            }
        }
        __syncthreads();
    }

    #pragma unroll
    for (int i = 0; i < 8; i++) {
        float* dst = C + (size_t)(ty * 8 + i) * ldc + tx * 8;
        ulonglong2 v0; v0.x = acc[i][0]; v0.y = acc[i][1];
        ulonglong2 v1; v1.x = acc[i][2]; v1.y = acc[i][3];
        *(ulonglong2*)(dst)     = v0;
        *(ulonglong2*)(dst + 4) = v1;
    }
}

// gather pair rows for step tnext
__device__ void gather_pair(int tnext, const float* __restrict__ x, const int* __restrict__ ping)
{
    const int idx0 = blockIdx.x * blockDim.x + threadIdx.x;
    const int stride = gridDim.x * blockDim.x;
    for (int idx = idx0; idx < 2 * B_ * H_; idx += stride) {
        int m = idx / H_, k = idx - m * H_;
        int b = m >> 1, s = m & 1;
        float val;
        if (s) {
            val = x[((size_t)tnext * B_ + b) * H_ + k];
        } else {
            int pt = ping[b * T_ + tnext];
            int i2 = pt - 1;
            i2 = i2 < 0 ? 0 : (i2 > T_ - 1 ? T_ - 1 : i2);
            const float* src = (i2 < tnext) ? g_newvAll : x;
            val = src[((size_t)i2 * B_ + b) * H_ + k];
        }
        g_pair[idx] = val;
    }
}

// ------------------------- persistent kernel -------------------------------
__global__ void __launch_bounds__(NTHREADS, 2)
sqac_kernel(const float* __restrict__ question, const float* __restrict__ answer,
            const float* __restrict__ x, const int* __restrict__ ping,
            const float* __restrict__ h0, const float* __restrict__ c0,
            const float* __restrict__ Wqh, const float* __restrict__ bqh,
            const float* __restrict__ Wah, const float* __restrict__ bah,
            const float* __restrict__ Wih, const float* __restrict__ bih,
            const float* __restrict__ Whh, const float* __restrict__ bhh,
            const float* __restrict__ Wq,  const float* __restrict__ bq,
            const float* __restrict__ Wk,  const float* __restrict__ bk,
            const float* __restrict__ Wv,  const float* __restrict__ bv,
            const float* __restrict__ Wfuse, const float* __restrict__ bfuse,
            float* __restrict__ out)
{
    __shared__ float As[2 * 16 * 128];   // 16 KB
    __shared__ float Bs[2 * 16 * 256];   // 32 KB

    const int idx0   = blockIdx.x * blockDim.x + threadIdx.x;
    const int stride = gridDim.x * blockDim.x;
    const int bid    = blockIdx.x;
    const int nblk   = gridDim.x;

    // ---- I0: state init + first gather ---------------------------------
    for (int idx = idx0; idx < B_ * H_; idx += stride) {
        g_h[idx] = h0[idx];
        g_c[idx] = c0[idx];
    }
    gather_pair(0, x, ping);
    gsync();

    // ---- I1: base partials (same decomposition as gates) ----------------
    for (int task = bid; task < 12 * SK_G; task += nblk) {
        int kc = task / 12, nt = task % 12;
        int n0 = nt * 256;
        gemm_db<64, 256>(As, Bs, question, answer, H_, H_,
                         Wqh + n0, Wah + n0, G4H,
                         kc * 64, 64, g_gp + (size_t)kc * (B_ * G4H) + n0, G4H);
    }
    gsync();

    // ---- I2: combine base + biases --------------------------------------
    for (int idx = idx0; idx < B_ * G4H; idx += stride) {
        int n = idx % G4H;
        float s = bqh[n] + bah[n] + bih[n] + bhh[n];
        #pragma unroll
        for (int kc = 0; kc < SK_G; kc++) s += g_gp[(size_t)kc * (B_ * G4H) + idx];
        g_base[idx] = s;
    }
    gsync();

    // =====================================================================
    for (int t = 0; t < T_; t++) {
        // ---- A: QKV GEMM, C(128 x 2304), K=768 --------------------------
        for (int task = bid; task < 18 * SK_QKV; task += nblk) {
            int kc = task / 18, nt = task % 18;
            int n0 = nt * 128;
            int wsel = n0 / H_;
            int ncol = n0 - wsel * H_;
            const float* Wb = (wsel == 0) ? Wq : ((wsel == 1) ? Wk : Wv);
            gemm_db<128, 128>(As, Bs, g_pair, g_pair, H_, 1 << 28,
                              Wb + ncol, Wb + ncol, H_,
                              kc * 96, 96,
                              g_qkvp + (size_t)kc * (2 * B_ * QKVW) + n0, QKVW);
        }
        gsync();

        // ---- B: attention (one warp per (b, head)) ----------------------
        {
            int wid = bid * (NTHREADS / 32) + (threadIdx.x >> 5);
            int lane = threadIdx.x & 31;
            for (int task = wid; task < B_ * NH_; task += nblk * (NTHREADS / 32)) {
                int b = task / NH_, h = task - b * NH_;
                float q[2][2], kk2[2][2], vv[2][2];
                #pragma unroll
                for (int s = 0; s < 2; s++) {
                    int row = (b * 2 + s) * QKVW;
                    #pragma unroll
                    for (int dd = 0; dd < 2; dd++) {
                        int d = lane + dd * 32;
                        int col = h * HD_ + d;
                        float qv = bq[col], kv = bk[col], vvv = bv[col];
                        #pragma unroll
                        for (int kc = 0; kc < SK_QKV; kc++) {
                            const float* p = g_qkvp + (size_t)kc * (2 * B_ * QKVW) + row;
                            qv  += p[col];
                            kv  += p[H_ + col];
                            vvv += p[2 * H_ + col];
                        }
                        q[s][dd] = qv; kk2[s][dd] = kv; vv[s][dd] = vvv;
                    }
                }
                float s00 = wsum(q[0][0]*kk2[0][0] + q[0][1]*kk2[0][1]) * 0.125f;
                float s01 = wsum(q[0][0]*kk2[1][0] + q[0][1]*kk2[1][1]) * 0.125f;
                float s10 = wsum(q[1][0]*kk2[0][0] + q[1][1]*kk2[0][1]) * 0.125f;
                float s11 = wsum(q[1][0]*kk2[1][0] + q[1][1]*kk2[1][1]) * 0.125f;
                float m0 = fmaxf(s00, s01), m1 = fmaxf(s10, s11);
                float e00 = expf(s00 - m0), e01 = expf(s01 - m0);
                float e10 = expf(s10 - m1), e11 = expf(s11 - m1);
                float r0 = 1.f / (e00 + e01), r1 = 1.f / (e10 + e11);
                float p00 = e00 * r0, p01 = e01 * r0, p10 = e10 * r1, p11 = e11 * r1;
                #pragma unroll
                for (int dd = 0; dd < 2; dd++) {
                    int d = lane + dd * 32;
                    g_ctx[b * (2*H_) + h * HD_ + d]      = p00 * vv[0][dd] + p01 * vv[1][dd];
                    g_ctx[b * (2*H_) + H_ + h * HD_ + d] = p10 * vv[0][dd] + p11 * vv[1][dd];
                }
            }
        }
        gsync();

        // ---- C: fuse GEMM, C(64 x 768), K=1536 ---------------------------
        for (int task = bid; task < 3 * SK_F; task += nblk) {
            int kc = task / 3, nt = task % 3;
            int n0 = nt * 256;
            gemm_db<64, 256>(As, Bs, g_ctx, g_ctx, 2 * H_, 1 << 28,
                             Wfuse + n0, Wfuse + n0, H_,
                             kc * 32, 32, g_fp + (size_t)kc * (B_ * H_) + n0, H_);
        }
        gsync();

        // ---- C2: combine + select + write newvAll[t] ---------------------
        for (int idx = idx0; idx < B_ * H_; idx += stride) {
            int b = idx / H_, j = idx - b * H_;
            float e = bfuse[j];
            #pragma unroll
            for (int kc = 0; kc < SK_F; kc++) e += g_fp[(size_t)kc * (B_ * H_) + idx];
            int pt = ping[b * T_ + t];
            float right = x[((size_t)t * B_ + b) * H_ + j];
            bool cond = (pt > 0) && (t > 0);
            g_newvAll[(size_t)t * (B_ * H_) + idx] = cond ? e : right;
        }
        gsync();

        // ---- D: gates GEMM, C(64 x 3072), A=[newv|h], K=1536 -------------
        for (int task = bid; task < 12 * SK_G; task += nblk) {
            int kc = task / 12, nt = task % 12;
            int n0 = nt * 256;
            gemm_db<64, 256>(As, Bs, g_newvAll + (size_t)t * (B_ * H_), g_h, H_, H_,
                             Wih + n0, Whh + n0, G4H,
                             kc * 64, 64, g_gp + (size_t)kc * (B_ * G4H) + n0, G4H);
        }
        gsync();

        // ---- E: LSTM pointwise + output + gather next pair ---------------
        for (int idx = idx0; idx < B_ * H_; idx += stride) {
            int b = idx / H_, j = idx - b * H_;
            float gg[4];
            #pragma unroll
            for (int u = 0; u < 4; u++) {
                int col = b * G4H + u * H_ + j;
                float s = g_base[col];
                #pragma unroll
                for (int kc = 0; kc < SK_G; kc++) s += g_gp[(size_t)kc * (B_ * G4H) + col];
                gg[u] = s;
            }
            float iv = sigm(gg[0]);
            float fv = sigm(gg[1]);
            float gv = tanhf(gg[2]);
            float ov = sigm(gg[3]);
            float c = fv * g_c[idx] + iv * gv;
            float h = ov * tanhf(c);
            g_c[idx] = c;
            g_h[idx] = h;
            out[((size_t)t * B_ + b) * H_ + j] = h;
            if (t == T_ - 1) {
                out[((size_t)T_ * B_ + b) * H_ + j]       = h;   // hT
                out[((size_t)(T_ + 1) * B_ + b) * H_ + j] = c;   // cT
            }
        }
        if (t + 1 < T_) gather_pair(t + 1, x, ping);
        gsync();
    }
}

// ------------------------- host launch --------------------------------------
extern "C" void kernel_launch(void* const* d_in, const int* in_sizes, int n_in,
                              void* d_out, int out_size)
{
    (void)in_sizes; (void)n_in; (void)out_size;
    const float* question = (const float*)d_in[0];
    const float* answer   = (const float*)d_in[1];
    const float* x        = (const float*)d_in[2];
    const int*   ping     = (const int*)  d_in[3];
    const float* h0       = (const float*)d_in[4];
    const float* c0       = (const float*)d_in[5];
    const float* Wqh      = (const float*)d_in[6];
    const float* bqh      = (const float*)d_in[7];
    const float* Wah      = (const float*)d_in[8];
    const float* bah      = (const float*)d_in[9];
    const float* Wih      = (const float*)d_in[10];
    const float* bih      = (const float*)d_in[11];
    const float* Whh      = (const float*)d_in[12];
    const float* bhh      = (const float*)d_in[13];
    const float* Wq       = (const float*)d_in[14];
    const float* bq       = (const float*)d_in[15];
    const float* Wk       = (const float*)d_in[16];
    const float* bk       = (const float*)d_in[17];
    const float* Wv       = (const float*)d_in[18];
    const float* bv       = (const float*)d_in[19];
    const float* Wfuse    = (const float*)d_in[20];
    const float* bfuse    = (const float*)d_in[21];

    int dev = 0;
    cudaGetDevice(&dev);
    int nsm = 148;
    cudaDeviceGetAttribute(&nsm, cudaDevAttrMultiProcessorCount, dev);
    int maxb = 1;
    cudaOccupancyMaxActiveBlocksPerMultiprocessor(&maxb, sqac_kernel, NTHREADS, 0);
    if (maxb < 1) maxb = 1;
    if (maxb > 2) maxb = 2;
    int grid = nsm * maxb;

    sqac_kernel<<<grid, NTHREADS>>>(question, answer, x, ping, h0, c0,
                                    Wqh, bqh, Wah, bah, Wih, bih, Whh, bhh,
                                    Wq, bq, Wk, bk, Wv, bv, Wfuse, bfuse,
                                    (float*)d_out);
}